// round 7
// baseline (speedup 1.0000x reference)
#include <cuda_runtime.h>
#include <cuda_fp16.h>
#include <stdint.h>

#define B_ 4
#define S_ 2048
#define D_ 1024
#define H_ 16
#define DK_ 64
#define MTOT (B_*S_)

// log2(e)/sqrt(DK): folded into Wq/bq so attention scores come out pre-scaled
#define SC_LOG2E 0.1803368801111204f

// fp16 staging buffers (device globals: allocation-free rule)
__device__ __half g_xq[MTOT*D_];
__device__ __half g_xk[MTOT*D_];
__device__ __half g_xv[MTOT*D_];
__device__ __half g_wq[D_*D_];
__device__ __half g_wk[D_*D_];
__device__ __half g_wv[D_*D_];
__device__ __half g_wo[D_*D_];
__device__ __half g_Q[MTOT*D_];
__device__ __half g_K[MTOT*D_];
__device__ __half g_V[MTOT*D_];
__device__ __half g_A[MTOT*D_];

// ---------------- PTX helpers ----------------
__device__ __forceinline__ float ex2f(float x){
  float r; asm("ex2.approx.ftz.f32 %0, %1;" : "=f"(r) : "f"(x)); return r;
}
__device__ __forceinline__ void ldsm4(uint32_t* r, uint32_t a){
  asm volatile("ldmatrix.sync.aligned.m8n8.x4.shared.b16 {%0,%1,%2,%3},[%4];"
    : "=r"(r[0]),"=r"(r[1]),"=r"(r[2]),"=r"(r[3]) : "r"(a));
}
__device__ __forceinline__ void ldsm4t(uint32_t* r, uint32_t a){
  asm volatile("ldmatrix.sync.aligned.m8n8.x4.trans.shared.b16 {%0,%1,%2,%3},[%4];"
    : "=r"(r[0]),"=r"(r[1]),"=r"(r[2]),"=r"(r[3]) : "r"(a));
}
__device__ __forceinline__ void mma16816(float* c, const uint32_t* a, uint32_t b0, uint32_t b1){
  asm volatile("mma.sync.aligned.m16n8k16.row.col.f32.f16.f16.f32 "
    "{%0,%1,%2,%3},{%4,%5,%6,%7},{%8,%9},{%0,%1,%2,%3};"
    : "+f"(c[0]),"+f"(c[1]),"+f"(c[2]),"+f"(c[3])
    : "r"(a[0]),"r"(a[1]),"r"(a[2]),"r"(a[3]),"r"(b0),"r"(b1));
}
__device__ __forceinline__ void cp16(uint32_t d, const void* s){
  asm volatile("cp.async.cg.shared.global [%0],[%1],16;" :: "r"(d),"l"(s));
}
#define CP_COMMIT() asm volatile("cp.async.commit_group;")
#define CP_WAIT(n)  asm volatile("cp.async.wait_group %0;" :: "n"(n))
__device__ __forceinline__ uint32_t h2u(float a, float b){
  __half2 h = __floats2half2_rn(a,b); return *(uint32_t*)&h;
}

// ---------------- fused fp32 -> fp16 conversion ----------------
template<int ITER>
__global__ void f2h_act(const float4* __restrict__ a0, const float4* __restrict__ a1,
                        const float4* __restrict__ a2,
                        uint2* __restrict__ o0, uint2* __restrict__ o1, uint2* __restrict__ o2){
  const float4* in; uint2* out;
  if (blockIdx.z == 0){ in=a0; out=o0; }
  else if (blockIdx.z == 1){ in=a1; out=o1; }
  else { in=a2; out=o2; }
  const int t = blockIdx.x*blockDim.x + threadIdx.x;
  const int stride = gridDim.x*blockDim.x;
  #pragma unroll
  for (int k=0;k<ITER;k++){
    const int i = t + k*stride;
    float4 v = in[i];
    uint2 u; u.x = h2u(v.x,v.y); u.y = h2u(v.z,v.w);
    out[i] = u;
  }
}

template<int ITER>
__global__ void f2h_w(const float4* __restrict__ a0, const float4* __restrict__ a1,
                      const float4* __restrict__ a2, const float4* __restrict__ a3,
                      uint2* __restrict__ o0, uint2* __restrict__ o1,
                      uint2* __restrict__ o2, uint2* __restrict__ o3, float s0){
  const float4* in; uint2* out; float sc = 1.f;
  if (blockIdx.z == 0){ in=a0; out=o0; sc=s0; }
  else if (blockIdx.z == 1){ in=a1; out=o1; }
  else if (blockIdx.z == 2){ in=a2; out=o2; }
  else { in=a3; out=o3; }
  const int t = blockIdx.x*blockDim.x + threadIdx.x;
  const int stride = gridDim.x*blockDim.x;
  #pragma unroll
  for (int k=0;k<ITER;k++){
    const int i = t + k*stride;
    float4 v = in[i];
    uint2 u; u.x = h2u(v.x*sc, v.y*sc); u.y = h2u(v.z*sc, v.w*sc);
    out[i] = u;
  }
}

// ---------------------------------------------------------------------------
// GEMM: Y[M,N] = X[M,K] @ W[N,K]^T + bias*bscale.  fp16 in, fp32 acc.
// 128x128x32 tiles, 8 warps (2x4), 4-stage cp.async pipeline, 1 sync/iter.
// ---------------------------------------------------------------------------
#define GST 40
#define STG (128*GST)                       // halves per tensor per stage
#define GEMM_STAGES 4
#define GEMM_SMEM (GEMM_STAGES*2*STG*2)     // 81920 bytes

template<bool HOUT>
__device__ __forceinline__ void gemm_body(
    const __half* __restrict__ X, const __half* __restrict__ W,
    const float* __restrict__ bias, float bscale, void* __restrict__ Yv,
    int M, int N, int K)
{
  extern __shared__ __half gsm[];
  const uint32_t as_base = (uint32_t)__cvta_generic_to_shared(gsm);
  const uint32_t bs_base = as_base + GEMM_STAGES*STG*2;

  const int tid = threadIdx.x;
  const int warp = tid >> 5, lane = tid & 31;
  const int wm = warp >> 2, wn = warp & 3;
  const int g = lane >> 2, q = lane & 3;
  const int bm = blockIdx.y * 128, bn = blockIdx.x * 128;

  float acc[4][4][4];
  #pragma unroll
  for (int i=0;i<4;i++)
    #pragma unroll
    for (int j=0;j<4;j++){ acc[i][j][0]=0.f; acc[i][j][1]=0.f; acc[i][j][2]=0.f; acc[i][j][3]=0.f; }

  const int lrow = tid >> 2, lsub = tid & 3;
  auto load_stage = [&](int s, int k0){
    #pragma unroll
    for (int i=0;i<2;i++){
      const int row = lrow + i*64;
      const uint32_t off = (uint32_t)(s*STG + row*GST + lsub*8)*2;
      cp16(as_base + off, X + (bm+row)*K + k0 + lsub*8);
      cp16(bs_base + off, W + (bn+row)*K + k0 + lsub*8);
    }
    CP_COMMIT();
  };

  load_stage(0, 0);
  load_stage(1, 32);
  load_stage(2, 64);

  const int KT = K / 32;                    // 32
  for (int kt=0; kt<KT; kt++){
    const int s = kt & (GEMM_STAGES-1);
    if (kt < KT-2)       { CP_WAIT(2); }
    else if (kt == KT-2) { CP_WAIT(1); }
    else                 { CP_WAIT(0); }
    __syncthreads();
    if (kt+3 < KT) load_stage((kt+3) & (GEMM_STAGES-1), (kt+3)*32);

    const uint32_t abase = as_base + (uint32_t)(s*STG)*2;
    const uint32_t bbase = bs_base + (uint32_t)(s*STG)*2;
    #pragma unroll
    for (int ks=0; ks<2; ks++){
      uint32_t af[4][4];
      #pragma unroll
      for (int mt=0; mt<4; mt++){
        uint32_t ad = abase +
          (uint32_t)(((wm*64 + mt*16 + (lane&15))*GST + ks*16 + (lane>>4)*8) << 1);
        ldsm4(af[mt], ad);
      }
      #pragma unroll
      for (int p=0; p<2; p++){
        uint32_t bf[4];
        uint32_t bd = bbase +
          (uint32_t)(((wn*32 + p*16 + ((lane>>4)<<3) + (lane&7))*GST + ks*16 + ((lane>>3)&1)*8) << 1);
        ldsm4(bf, bd);
        #pragma unroll
        for (int mt=0; mt<4; mt++){
          mma16816(acc[mt][2*p],   af[mt], bf[0], bf[1]);
          mma16816(acc[mt][2*p+1], af[mt], bf[2], bf[3]);
        }
      }
    }
  }

  #pragma unroll
  for (int mt=0; mt<4; mt++){
    const int r0 = bm + wm*64 + mt*16 + g;
    #pragma unroll
    for (int nt=0; nt<4; nt++){
      const int c = bn + wn*32 + nt*8 + 2*q;
      const float b0 = bias[c]*bscale, b1 = bias[c+1]*bscale;
      if (HOUT){
        __half* Y = (__half*)Yv;
        *(uint32_t*)&Y[r0*N + c]     = h2u(acc[mt][nt][0]+b0, acc[mt][nt][1]+b1);
        *(uint32_t*)&Y[(r0+8)*N + c] = h2u(acc[mt][nt][2]+b0, acc[mt][nt][3]+b1);
      } else {
        float* Y = (float*)Yv;
        *(float2*)&Y[r0*N + c]     = make_float2(acc[mt][nt][0]+b0, acc[mt][nt][1]+b1);
        *(float2*)&Y[(r0+8)*N + c] = make_float2(acc[mt][nt][2]+b0, acc[mt][nt][3]+b1);
      }
    }
  }
}

__global__ __launch_bounds__(256,2)
void proj3(const __half* x0, const __half* x1, const __half* x2,
           const __half* w0, const __half* w1, const __half* w2,
           const float* b0, const float* b1, const float* b2,
           __half* y0, __half* y1, __half* y2, int M, int N, int K){
  const __half* X[3] = {x0,x1,x2};
  const __half* W[3] = {w0,w1,w2};
  const float*  Bp[3] = {b0,b1,b2};
  __half* Y[3] = {y0,y1,y2};
  const int z = blockIdx.z;
  const float bs = (z == 0) ? SC_LOG2E : 1.f;   // Wq/bq carry softmax scale
  gemm_body<true>(X[z], W[z], Bp[z], bs, Y[z], M, N, K);
}

__global__ __launch_bounds__(256,2)
void gemm_out(const __half* X, const __half* W, const float* bias,
              float* Y, int M, int N, int K){
  gemm_body<false>(X, W, bias, 1.f, Y, M, N, K);
}

// ---------------------------------------------------------------------------
// Causal flash attention, fp16 mma + ldmatrix, P in registers.
// Split K/V commit groups: QK waits only on K, V wait deferred past softmax.
// ---------------------------------------------------------------------------
#define KVST  (128*72)
#define ABUF  (2*KVST)
#define ATT_SMEM (2*ABUF*2)

__global__ __launch_bounds__(256,1)
void attn_f16(const __half* __restrict__ Q, const __half* __restrict__ K,
              const __half* __restrict__ V, __half* __restrict__ O){
  extern __shared__ __half sm[];
  const uint32_t smb = (uint32_t)__cvta_generic_to_shared(sm);

  const int tid = threadIdx.x, warp = tid >> 5, lane = tid & 31;
  const int g = lane >> 2, q = lane & 3;
  const int bh = blockIdx.x;
  const int iq = gridDim.y - 1 - blockIdx.y;      // heavy tiles first
  const int b = bh >> 4, h = bh & 15;
  const int base = b * S_ * D_;
  const int hcol = h * DK_;
  const int qb = iq * 128;
  const int row0 = qb + warp*16 + g;
  const int row1 = row0 + 8;

  // persistent Q fragments: 4 k16-tiles (DK=64)
  uint32_t qf[4][4];
  {
    const __half* q0 = Q + base + (size_t)row0*D_ + hcol;
    const __half* q1 = q0 + 8*D_;
    #pragma unroll
    for (int kt=0; kt<4; kt++){
      qf[kt][0] = *(const uint32_t*)(q0 + kt*16 + 2*q);
      qf[kt][1] = *(const uint32_t*)(q1 + kt*16 + 2*q);
      qf[kt][2] = *(const uint32_t*)(q0 + kt*16 + 2*q + 8);
      qf[kt][3] = *(const uint32_t*)(q1 + kt*16 + 2*q + 8);
    }
  }

  float oacc[8][4];
  #pragma unroll
  for (int i=0;i<8;i++){ oacc[i][0]=0.f; oacc[i][1]=0.f; oacc[i][2]=0.f; oacc[i][3]=0.f; }
  float m0=-1e30f, m1=-1e30f, l0=0.f, l1=0.f;

  const int lrow = tid >> 3, lsub = tid & 7;
  auto load_k = [&](int buf, int kb){
    #pragma unroll
    for (int i=0;i<4;i++){
      const int row = lrow + i*32;
      const uint32_t off = (uint32_t)(buf*ABUF + row*72 + lsub*8)*2;
      cp16(smb + off, K + base + (size_t)(kb+row)*D_ + hcol + lsub*8);
    }
    CP_COMMIT();
  };
  auto load_v = [&](int buf, int kb){
    #pragma unroll
    for (int i=0;i<4;i++){
      const int row = lrow + i*32;
      const uint32_t off = (uint32_t)(buf*ABUF + row*72 + lsub*8)*2;
      cp16(smb + (KVST*2) + off, V + base + (size_t)(kb+row)*D_ + hcol + lsub*8);
    }
    CP_COMMIT();
  };

  load_k(0, 0);
  load_v(0, 0);
  for (int j=0; j<=iq; j++){
    const int buf = j & 1;
    CP_WAIT(1);                 // K_j ready (V_j may still be in flight)
    __syncthreads();
    const bool pre = (j < iq);
    if (pre){ load_k(buf^1, (j+1)*128); load_v(buf^1, (j+1)*128); }

    const uint32_t ksb = smb + (uint32_t)(buf*ABUF)*2;
    const uint32_t vsb = ksb + (uint32_t)(KVST)*2;

    // S = Q @ K^T  (m16 x n128 per warp), pre-scaled by log2e/sqrt(dk)
    float s[16][4];
    #pragma unroll
    for (int nt=0;nt<16;nt++){ s[nt][0]=0.f; s[nt][1]=0.f; s[nt][2]=0.f; s[nt][3]=0.f; }
    #pragma unroll
    for (int kt=0; kt<4; kt++){
      #pragma unroll
      for (int p=0; p<8; p++){
        uint32_t bf[4];
        uint32_t ad = ksb + (uint32_t)(((p*16 + ((lane>>4)<<3) + (lane&7))*72
                                        + kt*16 + ((lane>>3)&1)*8) << 1);
        ldsm4(bf, ad);
        mma16816(s[2*p],   qf[kt], bf[0], bf[1]);
        mma16816(s[2*p+1], qf[kt], bf[2], bf[3]);
      }
    }

    // causal mask (diagonal tile only) + row max
    const int kb = j*128;
    const bool diag = (j == iq);
    float mx0=-1e30f, mx1=-1e30f;
    #pragma unroll
    for (int nt=0; nt<16; nt++){
      const int c0 = kb + nt*8 + 2*q;
      float v0 = s[nt][0], v1 = s[nt][1], v2 = s[nt][2], v3 = s[nt][3];
      if (diag){
        if (c0   > row0) v0 = -1e30f;
        if (c0+1 > row0) v1 = -1e30f;
        if (c0   > row1) v2 = -1e30f;
        if (c0+1 > row1) v3 = -1e30f;
        s[nt][0]=v0; s[nt][1]=v1; s[nt][2]=v2; s[nt][3]=v3;
      }
      mx0 = fmaxf(mx0, fmaxf(v0,v1));
      mx1 = fmaxf(mx1, fmaxf(v2,v3));
    }
    mx0 = fmaxf(mx0, __shfl_xor_sync(0xffffffffu, mx0, 1));
    mx0 = fmaxf(mx0, __shfl_xor_sync(0xffffffffu, mx0, 2));
    mx1 = fmaxf(mx1, __shfl_xor_sync(0xffffffffu, mx1, 1));
    mx1 = fmaxf(mx1, __shfl_xor_sync(0xffffffffu, mx1, 2));
    const float mn0 = fmaxf(m0, mx0), mn1 = fmaxf(m1, mx1);
    const float a0 = ex2f(m0 - mn0), a1 = ex2f(m1 - mn1);
    m0 = mn0; m1 = mn1;
    #pragma unroll
    for (int nt=0; nt<8; nt++){
      oacc[nt][0]*=a0; oacc[nt][1]*=a0; oacc[nt][2]*=a1; oacc[nt][3]*=a1;
    }

    // exp -> P fragments in registers (C-layout == A-layout)
    uint32_t pa[8][4];
    float sum0=0.f, sum1=0.f;
    #pragma unroll
    for (int t=0; t<8; t++){
      float e00 = ex2f(s[2*t][0]-m0),   e01 = ex2f(s[2*t][1]-m0);
      float e02 = ex2f(s[2*t][2]-m1),   e03 = ex2f(s[2*t][3]-m1);
      float e10 = ex2f(s[2*t+1][0]-m0), e11 = ex2f(s[2*t+1][1]-m0);
      float e12 = ex2f(s[2*t+1][2]-m1), e13 = ex2f(s[2*t+1][3]-m1);
      sum0 += (e00+e01) + (e10+e11);
      sum1 += (e02+e03) + (e12+e13);
      pa[t][0] = h2u(e00,e01);
      pa[t][1] = h2u(e02,e03);
      pa[t][2] = h2u(e10,e11);
      pa[t][3] = h2u(e12,e13);
    }
    sum0 += __shfl_xor_sync(0xffffffffu, sum0, 1);
    sum0 += __shfl_xor_sync(0xffffffffu, sum0, 2);
    sum1 += __shfl_xor_sync(0xffffffffu, sum1, 1);
    sum1 += __shfl_xor_sync(0xffffffffu, sum1, 2);
    l0 = l0*a0 + sum0; l1 = l1*a1 + sum1;

    // V_j must be resident before PV
    if (pre){ CP_WAIT(2); } else { CP_WAIT(0); }
    __syncthreads();

    // O += P @ V   (k=128 keys, n=64 dims), V via ldmatrix.trans
    #pragma unroll
    for (int kt=0; kt<8; kt++){
      #pragma unroll
      for (int p=0; p<4; p++){
        uint32_t bf[4];
        uint32_t ad = vsb + (uint32_t)(((kt*16 + ((lane>>3)&1)*8 + (lane&7))*72
                                        + p*16 + ((lane>>4)<<3)) << 1);
        ldsm4t(bf, ad);
        mma16816(oacc[2*p],   pa[kt], bf[0], bf[1]);
        mma16816(oacc[2*p+1], pa[kt], bf[2], bf[3]);
      }
    }
  }

  const float i0 = 1.f/l0, i1 = 1.f/l1;
  __half* o0 = O + base + (size_t)row0*D_ + hcol;
  __half* o1 = O + base + (size_t)row1*D_ + hcol;
  #pragma unroll
  for (int nt=0; nt<8; nt++){
    const int c = nt*8 + 2*q;
    *(uint32_t*)&o0[c] = h2u(oacc[nt][0]*i0, oacc[nt][1]*i0);
    *(uint32_t*)&o1[c] = h2u(oacc[nt][2]*i1, oacc[nt][3]*i1);
  }
}

// ---------------------------------------------------------------------------
extern "C" void kernel_launch(void* const* d_in, const int* in_sizes, int n_in,
                              void* d_out, int out_size){
  const float* xq = (const float*)d_in[0];
  const float* xk = (const float*)d_in[1];
  const float* xv = (const float*)d_in[2];
  const float* Wq = (const float*)d_in[3];
  const float* bq = (const float*)d_in[4];
  const float* Wk = (const float*)d_in[5];
  const float* bk = (const float*)d_in[6];
  const float* Wv = (const float*)d_in[7];
  const float* bv = (const float*)d_in[8];
  const float* Wo = (const float*)d_in[9];
  const float* bo = (const float*)d_in[10];
  float* out = (float*)d_out;

  __half *hxq,*hxk,*hxv,*hwq,*hwk,*hwv,*hwo,*hQ,*hK,*hV,*hA;
  cudaGetSymbolAddress((void**)&hxq, g_xq);
  cudaGetSymbolAddress((void**)&hxk, g_xk);
  cudaGetSymbolAddress((void**)&hxv, g_xv);
  cudaGetSymbolAddress((void**)&hwq, g_wq);
  cudaGetSymbolAddress((void**)&hwk, g_wk);
  cudaGetSymbolAddress((void**)&hwv, g_wv);
  cudaGetSymbolAddress((void**)&hwo, g_wo);
  cudaGetSymbolAddress((void**)&hQ, g_Q);
  cudaGetSymbolAddress((void**)&hK, g_K);
  cudaGetSymbolAddress((void**)&hV, g_V);
  cudaGetSymbolAddress((void**)&hA, g_A);

  cudaFuncSetAttribute(attn_f16, cudaFuncAttributeMaxDynamicSharedMemorySize, ATT_SMEM);
  cudaFuncSetAttribute(proj3, cudaFuncAttributeMaxDynamicSharedMemorySize, GEMM_SMEM);
  cudaFuncSetAttribute(gemm_out, cudaFuncAttributeMaxDynamicSharedMemorySize, GEMM_SMEM);

  // activations: 3 x 2M float4 -> grid 2048x256 threads x 4 iters
  f2h_act<4><<<dim3(2048,1,3), 256>>>(
      (const float4*)xq, (const float4*)xk, (const float4*)xv,
      (uint2*)hxq, (uint2*)hxk, (uint2*)hxv);
  // weights: 4 x 256K float4 -> grid 256x256 threads x 4 iters; Wq carries scale
  f2h_w<4><<<dim3(256,1,4), 256>>>(
      (const float4*)Wq, (const float4*)Wk, (const float4*)Wv, (const float4*)Wo,
      (uint2*)hwq, (uint2*)hwk, (uint2*)hwv, (uint2*)hwo, SC_LOG2E);

  proj3<<<dim3(D_/128, MTOT/128, 3), 256, GEMM_SMEM>>>(
      hxq,hxk,hxv, hwq,hwk,hwv, bq,bk,bv, hQ,hK,hV, MTOT, D_, D_);
  attn_f16<<<dim3(B_*H_, S_/128), 256, ATT_SMEM>>>(hQ, hK, hV, hA);
  gemm_out<<<dim3(D_/128, MTOT/128), 256, GEMM_SMEM>>>(hA, hwo, bo, out, MTOT, D_, D_);
}

// round 14
// speedup vs baseline: 1.0450x; 1.0450x over previous
#include <cuda_runtime.h>
#include <cuda_fp16.h>
#include <stdint.h>

#define B_ 4
#define S_ 2048
#define D_ 1024
#define H_ 16
#define DK_ 64
#define MTOT (B_*S_)

// log2(e)/sqrt(DK): folded into Wq/bq so attention scores come out pre-scaled
#define SC_LOG2E 0.1803368801111204f

// fp16 staging buffers (device globals: allocation-free rule)
__device__ __half g_xq[MTOT*D_];
__device__ __half g_xk[MTOT*D_];
__device__ __half g_xv[MTOT*D_];
__device__ __half g_wq[D_*D_];
__device__ __half g_wk[D_*D_];
__device__ __half g_wv[D_*D_];
__device__ __half g_wo[D_*D_];
__device__ __half g_Q[MTOT*D_];
__device__ __half g_K[MTOT*D_];
__device__ __half g_V[MTOT*D_];
__device__ __half g_A[MTOT*D_];

// ---------------- PTX helpers ----------------
__device__ __forceinline__ float ex2f(float x){
  float r; asm("ex2.approx.ftz.f32 %0, %1;" : "=f"(r) : "f"(x)); return r;
}
__device__ __forceinline__ void ldsm4(uint32_t* r, uint32_t a){
  asm volatile("ldmatrix.sync.aligned.m8n8.x4.shared.b16 {%0,%1,%2,%3},[%4];"
    : "=r"(r[0]),"=r"(r[1]),"=r"(r[2]),"=r"(r[3]) : "r"(a));
}
__device__ __forceinline__ void ldsm4t(uint32_t* r, uint32_t a){
  asm volatile("ldmatrix.sync.aligned.m8n8.x4.trans.shared.b16 {%0,%1,%2,%3},[%4];"
    : "=r"(r[0]),"=r"(r[1]),"=r"(r[2]),"=r"(r[3]) : "r"(a));
}
__device__ __forceinline__ void mma16816(float* c, const uint32_t* a, uint32_t b0, uint32_t b1){
  asm volatile("mma.sync.aligned.m16n8k16.row.col.f32.f16.f16.f32 "
    "{%0,%1,%2,%3},{%4,%5,%6,%7},{%8,%9},{%0,%1,%2,%3};"
    : "+f"(c[0]),"+f"(c[1]),"+f"(c[2]),"+f"(c[3])
    : "r"(a[0]),"r"(a[1]),"r"(a[2]),"r"(a[3]),"r"(b0),"r"(b1));
}
__device__ __forceinline__ void cp16(uint32_t d, const void* s){
  asm volatile("cp.async.cg.shared.global [%0],[%1],16;" :: "r"(d),"l"(s));
}
#define CP_COMMIT() asm volatile("cp.async.commit_group;")
#define CP_WAIT(n)  asm volatile("cp.async.wait_group %0;" :: "n"(n))
__device__ __forceinline__ uint32_t h2u(float a, float b){
  __half2 h = __floats2half2_rn(a,b); return *(uint32_t*)&h;
}

// ---------------- fused fp32 -> fp16 conversion ----------------
template<int ITER>
__global__ void f2h_act(const float4* __restrict__ a0, const float4* __restrict__ a1,
                        const float4* __restrict__ a2,
                        uint2* __restrict__ o0, uint2* __restrict__ o1, uint2* __restrict__ o2){
  const float4* in; uint2* out;
  if (blockIdx.z == 0){ in=a0; out=o0; }
  else if (blockIdx.z == 1){ in=a1; out=o1; }
  else { in=a2; out=o2; }
  const int t = blockIdx.x*blockDim.x + threadIdx.x;
  const int stride = gridDim.x*blockDim.x;
  #pragma unroll
  for (int k=0;k<ITER;k++){
    const int i = t + k*stride;
    float4 v = in[i];
    uint2 u; u.x = h2u(v.x,v.y); u.y = h2u(v.z,v.w);
    out[i] = u;
  }
}

template<int ITER>
__global__ void f2h_w(const float4* __restrict__ a0, const float4* __restrict__ a1,
                      const float4* __restrict__ a2, const float4* __restrict__ a3,
                      uint2* __restrict__ o0, uint2* __restrict__ o1,
                      uint2* __restrict__ o2, uint2* __restrict__ o3, float s0){
  const float4* in; uint2* out; float sc = 1.f;
  if (blockIdx.z == 0){ in=a0; out=o0; sc=s0; }
  else if (blockIdx.z == 1){ in=a1; out=o1; }
  else if (blockIdx.z == 2){ in=a2; out=o2; }
  else { in=a3; out=o3; }
  const int t = blockIdx.x*blockDim.x + threadIdx.x;
  const int stride = gridDim.x*blockDim.x;
  #pragma unroll
  for (int k=0;k<ITER;k++){
    const int i = t + k*stride;
    float4 v = in[i];
    uint2 u; u.x = h2u(v.x*sc, v.y*sc); u.y = h2u(v.z*sc, v.w*sc);
    out[i] = u;
  }
}

// ---------------------------------------------------------------------------
// GEMM (round-4 known-good): Y[M,N] = X[M,K] @ W[N,K]^T + bias*bscale.
// fp16 in, fp32 acc. 128x128x32 tiles, 8 warps (2x4), cp.async 2-stage,
// ldmatrix fragments.  Smem stride 40 halves -> conflict-free ldsm.
// ---------------------------------------------------------------------------
#define GST 40
#define GSTG_B (128*GST*2)

template<bool HOUT>
__device__ __forceinline__ void gemm_body(
    const __half* __restrict__ X, const __half* __restrict__ W,
    const float* __restrict__ bias, float bscale, void* __restrict__ Yv,
    int M, int N, int K)
{
  __shared__ __half As[2][128*GST];
  __shared__ __half Bs[2][128*GST];
  const int tid = threadIdx.x;
  const int warp = tid >> 5, lane = tid & 31;
  const int wm = warp >> 2, wn = warp & 3;
  const int g = lane >> 2, q = lane & 3;
  const int bm = blockIdx.y * 128, bn = blockIdx.x * 128;

  const uint32_t as_base = (uint32_t)__cvta_generic_to_shared(&As[0][0]);
  const uint32_t bs_base = (uint32_t)__cvta_generic_to_shared(&Bs[0][0]);

  float acc[4][4][4];
  #pragma unroll
  for (int i=0;i<4;i++)
    #pragma unroll
    for (int j=0;j<4;j++){ acc[i][j][0]=0.f; acc[i][j][1]=0.f; acc[i][j][2]=0.f; acc[i][j][3]=0.f; }

  const int lrow = tid >> 2, lsub = tid & 3;
  auto load_stage = [&](int s, int k0){
    #pragma unroll
    for (int i=0;i<2;i++){
      const int row = lrow + i*64;
      const uint32_t off = (uint32_t)(row*GST + lsub*8)*2 + s*GSTG_B;
      cp16(as_base + off, X + (bm+row)*K + k0 + lsub*8);
      cp16(bs_base + off, W + (bn+row)*K + k0 + lsub*8);
    }
    CP_COMMIT();
  };

  load_stage(0, 0);
  const int KT = K / 32;
  for (int kt=0; kt<KT; kt++){
    const int s = kt & 1;
    CP_WAIT(0);
    __syncthreads();
    if (kt+1 < KT) load_stage(s^1, (kt+1)*32);

    #pragma unroll
    for (int ks=0; ks<2; ks++){
      uint32_t af[4][4];
      #pragma unroll
      for (int mt=0; mt<4; mt++){
        uint32_t ad = as_base + s*GSTG_B +
          (uint32_t)(((wm*64 + mt*16 + (lane&15))*GST + ks*16 + (lane>>4)*8) << 1);
        ldsm4(af[mt], ad);
      }
      #pragma unroll
      for (int p=0; p<2; p++){
        uint32_t bf[4];
        uint32_t bd = bs_base + s*GSTG_B +
          (uint32_t)(((wn*32 + p*16 + ((lane>>4)<<3) + (lane&7))*GST + ks*16 + ((lane>>3)&1)*8) << 1);
        ldsm4(bf, bd);
        #pragma unroll
        for (int mt=0; mt<4; mt++){
          mma16816(acc[mt][2*p],   af[mt], bf[0], bf[1]);
          mma16816(acc[mt][2*p+1], af[mt], bf[2], bf[3]);
        }
      }
    }
    __syncthreads();
  }

  #pragma unroll
  for (int mt=0; mt<4; mt++){
    const int r0 = bm + wm*64 + mt*16 + g;
    #pragma unroll
    for (int nt=0; nt<4; nt++){
      const int c = bn + wn*32 + nt*8 + 2*q;
      const float b0 = bias[c]*bscale, b1 = bias[c+1]*bscale;
      if (HOUT){
        __half* Y = (__half*)Yv;
        *(uint32_t*)&Y[r0*N + c]     = h2u(acc[mt][nt][0]+b0, acc[mt][nt][1]+b1);
        *(uint32_t*)&Y[(r0+8)*N + c] = h2u(acc[mt][nt][2]+b0, acc[mt][nt][3]+b1);
      } else {
        float* Y = (float*)Yv;
        *(float2*)&Y[r0*N + c]     = make_float2(acc[mt][nt][0]+b0, acc[mt][nt][1]+b1);
        *(float2*)&Y[(r0+8)*N + c] = make_float2(acc[mt][nt][2]+b0, acc[mt][nt][3]+b1);
      }
    }
  }
}

__global__ __launch_bounds__(256,2)
void proj3(const __half* x0, const __half* x1, const __half* x2,
           const __half* w0, const __half* w1, const __half* w2,
           const float* b0, const float* b1, const float* b2,
           __half* y0, __half* y1, __half* y2, int M, int N, int K){
  const __half* X[3] = {x0,x1,x2};
  const __half* W[3] = {w0,w1,w2};
  const float*  Bp[3] = {b0,b1,b2};
  __half* Y[3] = {y0,y1,y2};
  const int z = blockIdx.z;
  const float bs = (z == 0) ? SC_LOG2E : 1.f;   // Wq/bq carry softmax scale
  gemm_body<true>(X[z], W[z], Bp[z], bs, Y[z], M, N, K);
}

__global__ __launch_bounds__(256,2)
void gemm_out(const __half* X, const __half* W, const float* bias,
              float* Y, int M, int N, int K){
  gemm_body<false>(X, W, bias, 1.f, Y, M, N, K);
}

// ---------------------------------------------------------------------------
// Causal flash attention: q-tile 64, 4 warps (128 thr), 2 CTAs/SM.
// KV tiles of 128 rows double-buffered via cp.async; fp16 mma + ldmatrix;
// P in registers; heavy q-tiles scheduled first.
// ---------------------------------------------------------------------------
#define KVST  (128*72)            // halves per tensor per buffer
#define ABUF  (2*KVST)            // halves per buffer (K then V)
#define ATT_SMEM (2*ABUF*2)       // 73728 bytes

__global__ __launch_bounds__(128,2)
void attn_f16(const __half* __restrict__ Q, const __half* __restrict__ K,
              const __half* __restrict__ V, __half* __restrict__ O){
  extern __shared__ __half sm[];
  const uint32_t smb = (uint32_t)__cvta_generic_to_shared(sm);

  const int tid = threadIdx.x, warp = tid >> 5, lane = tid & 31;
  const int g = lane >> 2, q = lane & 3;
  const int bh = blockIdx.x;
  const int iq = gridDim.y - 1 - blockIdx.y;      // heavy q-tiles first
  const int b = bh >> 4, h = bh & 15;
  const int base = b * S_ * D_;
  const int hcol = h * DK_;
  const int qb = iq * 64;
  const int row0 = qb + warp*16 + g;
  const int row1 = row0 + 8;
  const int jmax = iq >> 1;                       // last (possibly partial) KV tile

  // persistent Q fragments: 4 k16-tiles (DK=64)
  uint32_t qf[4][4];
  {
    const __half* q0 = Q + base + (size_t)row0*D_ + hcol;
    const __half* q1 = q0 + 8*D_;
    #pragma unroll
    for (int kt=0; kt<4; kt++){
      qf[kt][0] = *(const uint32_t*)(q0 + kt*16 + 2*q);
      qf[kt][1] = *(const uint32_t*)(q1 + kt*16 + 2*q);
      qf[kt][2] = *(const uint32_t*)(q0 + kt*16 + 2*q + 8);
      qf[kt][3] = *(const uint32_t*)(q1 + kt*16 + 2*q + 8);
    }
  }

  float oacc[8][4];
  #pragma unroll
  for (int i=0;i<8;i++){ oacc[i][0]=0.f; oacc[i][1]=0.f; oacc[i][2]=0.f; oacc[i][3]=0.f; }
  float m0=-1e30f, m1=-1e30f, l0=0.f, l1=0.f;

  const int lrow = tid >> 3, lsub = tid & 7;      // 128 thr: 16 rows x 8 chunks
  auto load_tile = [&](int buf, int kb){
    #pragma unroll
    for (int i=0;i<8;i++){
      const int row = lrow + i*16;
      const uint32_t off = (uint32_t)(buf*ABUF + row*72 + lsub*8)*2;
      cp16(smb + off,            K + base + (size_t)(kb+row)*D_ + hcol + lsub*8);
      cp16(smb + (KVST*2) + off, V + base + (size_t)(kb+row)*D_ + hcol + lsub*8);
    }
    CP_COMMIT();
  };

  load_tile(0, 0);
  for (int j=0; j<=jmax; j++){
    const int buf = j & 1;
    CP_WAIT(0);
    __syncthreads();
    if (j < jmax) load_tile(buf^1, (j+1)*128);

    const uint32_t ksb = smb + (uint32_t)(buf*ABUF)*2;
    const uint32_t vsb = ksb + (uint32_t)(KVST)*2;

    // S = Q @ K^T  (m16 x n128 per warp), pre-scaled by log2e/sqrt(dk)
    float s[16][4];
    #pragma unroll
    for (int nt=0;nt<16;nt++){ s[nt][0]=0.f; s[nt][1]=0.f; s[nt][2]=0.f; s[nt][3]=0.f; }
    #pragma unroll
    for (int kt=0; kt<4; kt++){
      #pragma unroll
      for (int p=0; p<8; p++){
        uint32_t bf[4];
        uint32_t ad = ksb + (uint32_t)(((p*16 + ((lane>>4)<<3) + (lane&7))*72
                                        + kt*16 + ((lane>>3)&1)*8) << 1);
        ldsm4(bf, ad);
        mma16816(s[2*p],   qf[kt], bf[0], bf[1]);
        mma16816(s[2*p+1], qf[kt], bf[2], bf[3]);
      }
    }

    // causal mask (last KV tile only) + row max
    const int kb = j*128;
    const bool diag = (j == jmax);
    float mx0=-1e30f, mx1=-1e30f;
    #pragma unroll
    for (int nt=0; nt<16; nt++){
      const int c0 = kb + nt*8 + 2*q;
      float v0 = s[nt][0], v1 = s[nt][1], v2 = s[nt][2], v3 = s[nt][3];
      if (diag){
        if (c0   > row0) v0 = -1e30f;
        if (c0+1 > row0) v1 = -1e30f;
        if (c0   > row1) v2 = -1e30f;
        if (c0+1 > row1) v3 = -1e30f;
        s[nt][0]=v0; s[nt][1]=v1; s[nt][2]=v2; s[nt][3]=v3;
      }
      mx0 = fmaxf(mx0, fmaxf(v0,v1));
      mx1 = fmaxf(mx1, fmaxf(v2,v3));
    }
    mx0 = fmaxf(mx0, __shfl_xor_sync(0xffffffffu, mx0, 1));
    mx0 = fmaxf(mx0, __shfl_xor_sync(0xffffffffu, mx0, 2));
    mx1 = fmaxf(mx1, __shfl_xor_sync(0xffffffffu, mx1, 1));
    mx1 = fmaxf(mx1, __shfl_xor_sync(0xffffffffu, mx1, 2));
    const float mn0 = fmaxf(m0, mx0), mn1 = fmaxf(m1, mx1);
    const float a0 = ex2f(m0 - mn0), a1 = ex2f(m1 - mn1);
    m0 = mn0; m1 = mn1;
    #pragma unroll
    for (int nt=0; nt<8; nt++){
      oacc[nt][0]*=a0; oacc[nt][1]*=a0; oacc[nt][2]*=a1; oacc[nt][3]*=a1;
    }

    // exp -> P fragments in registers (C-layout == A-layout)
    uint32_t pa[8][4];
    float sum0=0.f, sum1=0.f;
    #pragma unroll
    for (int t=0; t<8; t++){
      float e00 = ex2f(s[2*t][0]-m0),   e01 = ex2f(s[2*t][1]-m0);
      float e02 = ex2f(s[2*t][2]-m1),   e03 = ex2f(s[2*t][3]-m1);
      float e10 = ex2f(s[2*t+1][0]-m0), e11 = ex2f(s[2*t+1][1]-m0);
      float e12 = ex2f(s[2*t+1][2]-m1), e13 = ex2f(s[2*t+1][3]-m1);
      sum0 += (e00+e01) + (e10+e11);
      sum1 += (e02+e03) + (e12+e13);
      pa[t][0] = h2u(e00,e01);
      pa[t][1] = h2u(e02,e03);
      pa[t][2] = h2u(e10,e11);
      pa[t][3] = h2u(e12,e13);
    }
    sum0 += __shfl_xor_sync(0xffffffffu, sum0, 1);
    sum0 += __shfl_xor_sync(0xffffffffu, sum0, 2);
    sum1 += __shfl_xor_sync(0xffffffffu, sum1, 1);
    sum1 += __shfl_xor_sync(0xffffffffu, sum1, 2);
    l0 = l0*a0 + sum0; l1 = l1*a1 + sum1;

    // O += P @ V   (k=128 keys, n=64 dims), V via ldmatrix.trans
    #pragma unroll
    for (int kt=0; kt<8; kt++){
      #pragma unroll
      for (int p=0; p<4; p++){
        uint32_t bf[4];
        uint32_t ad = vsb + (uint32_t)(((kt*16 + ((lane>>3)&1)*8 + (lane&7))*72
                                        + p*16 + ((lane>>4)<<3)) << 1);
        ldsm4t(bf, ad);
        mma16816(oacc[2*p],   pa[kt], bf[0], bf[1]);
        mma16816(oacc[2*p+1], pa[kt], bf[2], bf[3]);
      }
    }
  }

  const float i0 = 1.f/l0, i1 = 1.f/l1;
  __half* o0 = O + base + (size_t)row0*D_ + hcol;
  __half* o1 = O + base + (size_t)row1*D_ + hcol;
  #pragma unroll
  for (int nt=0; nt<8; nt++){
    const int c = nt*8 + 2*q;
    *(uint32_t*)&o0[c] = h2u(oacc[nt][0]*i0, oacc[nt][1]*i0);
    *(uint32_t*)&o1[c] = h2u(oacc[nt][2]*i1, oacc[nt][3]*i1);
  }
}

// ---------------------------------------------------------------------------
extern "C" void kernel_launch(void* const* d_in, const int* in_sizes, int n_in,
                              void* d_out, int out_size){
  const float* xq = (const float*)d_in[0];
  const float* xk = (const float*)d_in[1];
  const float* xv = (const float*)d_in[2];
  const float* Wq = (const float*)d_in[3];
  const float* bq = (const float*)d_in[4];
  const float* Wk = (const float*)d_in[5];
  const float* bk = (const float*)d_in[6];
  const float* Wv = (const float*)d_in[7];
  const float* bv = (const float*)d_in[8];
  const float* Wo = (const float*)d_in[9];
  const float* bo = (const float*)d_in[10];
  float* out = (float*)d_out;

  __half *hxq,*hxk,*hxv,*hwq,*hwk,*hwv,*hwo,*hQ,*hK,*hV,*hA;
  cudaGetSymbolAddress((void**)&hxq, g_xq);
  cudaGetSymbolAddress((void**)&hxk, g_xk);
  cudaGetSymbolAddress((void**)&hxv, g_xv);
  cudaGetSymbolAddress((void**)&hwq, g_wq);
  cudaGetSymbolAddress((void**)&hwk, g_wk);
  cudaGetSymbolAddress((void**)&hwv, g_wv);
  cudaGetSymbolAddress((void**)&hwo, g_wo);
  cudaGetSymbolAddress((void**)&hQ, g_Q);
  cudaGetSymbolAddress((void**)&hK, g_K);
  cudaGetSymbolAddress((void**)&hV, g_V);
  cudaGetSymbolAddress((void**)&hA, g_A);

  cudaFuncSetAttribute(attn_f16, cudaFuncAttributeMaxDynamicSharedMemorySize, ATT_SMEM);

  // activations: 3 x 2M float4 -> grid 2048x256 threads x 4 iters
  f2h_act<4><<<dim3(2048,1,3), 256>>>(
      (const float4*)xq, (const float4*)xk, (const float4*)xv,
      (uint2*)hxq, (uint2*)hxk, (uint2*)hxv);
  // weights: 4 x 256K float4 -> grid 256x256 threads x 4 iters; Wq carries scale
  f2h_w<4><<<dim3(256,1,4), 256>>>(
      (const float4*)Wq, (const float4*)Wk, (const float4*)Wv, (const float4*)Wo,
      (uint2*)hwq, (uint2*)hwk, (uint2*)hwv, (uint2*)hwo, SC_LOG2E);

  proj3<<<dim3(D_/128, MTOT/128, 3), 256>>>(hxq,hxk,hxv, hwq,hwk,hwv,
                                            bq,bk,bv, hQ,hK,hV, MTOT, D_, D_);
  attn_f16<<<dim3(B_*H_, S_/64), 128, ATT_SMEM>>>(hQ, hK, hV, hA);
  gemm_out<<<dim3(D_/128, MTOT/128), 256>>>(hA, hwo, bo, out, MTOT, D_, D_);
}